// round 2
// baseline (speedup 1.0000x reference)
#include <cuda_runtime.h>

// Problem constants
#define BATCH      8192
#define N_AGENTS   96
#define M_ROWS     97      // N_AGENTS + 1 (new_self row 0)
#define SELF_DIM   16
#define H_DIM      48      // HUMAN_DIM
#define XS_STRIDE  49      // padded (odd) -> conflict-free column access
#define NTHREADS   512

// SMEM layout (floats). Every region base MUST be 16B (4-float) aligned:
// float4 LDS/STS on a misaligned base traps (misaligned address).
#define ALIGN4(x) (((x) + 3) & ~3)
#define OFF_XS   0                                   // [97][49] = 4753
#define OFF_A    ALIGN4(OFF_XS + 97*49)              // [97][97] = 9409
#define OFF_Z    ALIGN4(OFF_A + 97*97)               // [97][64] = 6208
#define OFF_R1   ALIGN4(OFF_Z + 97*64)               // [97][64] (Y stride48, then h1 stride64)
#define OFF_WA   ALIGN4(OFF_R1 + 97*64)              // [48][48] = 2304
#define OFF_W1   ALIGN4(OFF_WA + 48*48)              // [48][64] = 3072
#define OFF_SML  ALIGN4(OFF_W1 + 48*64)              // small scratch
#define SMEM_FLOATS (OFF_SML + 216)

__global__ __launch_bounds__(NTHREADS, 1)
void value_net_kernel(const float* __restrict__ state,
                      const float* __restrict__ t_w1, const float* __restrict__ t_b1,
                      const float* __restrict__ t_w2, const float* __restrict__ t_b2,
                      const float* __restrict__ w_a_g, const float* __restrict__ w1_g,
                      const float* __restrict__ w2_g,  const float* __restrict__ v_w1,
                      const float* __restrict__ v_b1,  const float* __restrict__ v_w2,
                      const float* __restrict__ v_b2,  float* __restrict__ out)
{
    extern __shared__ float sm[];
    float* Xs   = sm + OFF_XS;     // [97][49]
    float* A    = sm + OFF_A;      // [97][97]
    float* Z    = sm + OFF_Z;      // [97][64]
    float* R1   = sm + OFF_R1;     // Y [97][48] then h1 [97][64]
    float* wa   = sm + OFF_WA;     // [48][48]
    float* w1s  = sm + OFF_W1;     // [48][64]
    float* s_self = sm + OFF_SML;        // 16
    float* h50    = sm + OFF_SML + 16;   // 64 (uses 50)
    float* vv     = sm + OFF_SML + 80;   // 64
    float* feat   = sm + OFF_SML + 144;  // 64
    float* part   = sm + OFF_SML + 208;  // 2 warp partials (disjoint from feat)

    const int tid = threadIdx.x;
    const int b   = blockIdx.x;
    const float* st = state + (size_t)b * N_AGENTS * 64;

    // ---- Phase 0: load human rows -> Xs[1..96][0..47], weights, self_state ----
    for (int t = tid; t < N_AGENTS * 12; t += NTHREADS) {
        int r = t / 12, c = t % 12;
        float4 v4 = *(const float4*)(st + r * 64 + SELF_DIM + c * 4);
        float* dst = Xs + (r + 1) * XS_STRIDE + c * 4;   // scalar stores: stride 49 is odd
        dst[0] = v4.x; dst[1] = v4.y; dst[2] = v4.z; dst[3] = v4.w;
    }
    for (int t = tid; t < 48 * 48; t += NTHREADS) wa[t]  = w_a_g[t];
    for (int t = tid; t < 48 * 64; t += NTHREADS) w1s[t] = w1_g[t];
    if (tid < SELF_DIM) s_self[tid] = st[tid];
    __syncthreads();

    // ---- Phase 1: tiny MLP: h = relu(self @ t_w1 + t_b1) ----
    if (tid < 50) {
        float acc = t_b1[tid];
        #pragma unroll
        for (int k = 0; k < 16; k++) acc += s_self[k] * t_w1[k * 50 + tid];
        h50[tid] = fmaxf(acc, 0.f);
    }
    __syncthreads();
    // new_self = relu(h @ t_w2 + t_b2) -> Xs row 0
    if (tid < 48) {
        float acc = t_b2[tid];
        #pragma unroll 5
        for (int k = 0; k < 50; k++) acc += h50[k] * t_w2[k * 48 + tid];
        Xs[tid] = fmaxf(acc, 0.f);
    }
    __syncthreads();

    // ---- Phase 2: Y = X @ w_a  -> R1 (stride 48) ----
    for (int t = tid; t < M_ROWS * 12; t += NTHREADS) {
        int n = t / 12, jc = t % 12;
        float a0 = 0, a1 = 0, a2 = 0, a3 = 0;
        const float* xr = Xs + n * XS_STRIDE;
        const float* wc = wa + jc * 4;
        #pragma unroll 4
        for (int k = 0; k < 48; k++) {
            float xv = xr[k];
            const float* w4 = wc + k * 48;
            a0 += xv * w4[0]; a1 += xv * w4[1]; a2 += xv * w4[2]; a3 += xv * w4[3];
        }
        *(float4*)(R1 + n * 48 + jc * 4) = make_float4(a0, a1, a2, a3);
    }
    __syncthreads();

    // ---- Phase 3: S = Y @ X^T, row softmax -> A ----
    {
        int warp = tid >> 5, lane = tid & 31;
        for (int n = warp; n < M_ROWS; n += 16) {
            const float* yr = R1 + n * 48;
            const float* x0 = Xs + lane * XS_STRIDE;
            const float* x1 = Xs + (lane + 32) * XS_STRIDE;
            const float* x2 = Xs + (lane + 64) * XS_STRIDE;
            const float* x3 = Xs + 96 * XS_STRIDE;      // broadcast row
            float s0 = 0, s1 = 0, s2 = 0, s3 = 0;
            #pragma unroll 4
            for (int k = 0; k < 48; k++) {
                float yv = yr[k];
                s0 += yv * x0[k];
                s1 += yv * x1[k];
                s2 += yv * x2[k];
                s3 += yv * x3[k];
            }
            float mx = fmaxf(fmaxf(s0, s1), s2);
            if (lane == 0) mx = fmaxf(mx, s3);
            #pragma unroll
            for (int o = 16; o; o >>= 1) mx = fmaxf(mx, __shfl_xor_sync(~0u, mx, o));
            float e0 = __expf(s0 - mx), e1 = __expf(s1 - mx), e2 = __expf(s2 - mx);
            float e3 = __expf(s3 - mx);
            float sum = e0 + e1 + e2 + ((lane == 0) ? e3 : 0.f);
            #pragma unroll
            for (int o = 16; o; o >>= 1) sum += __shfl_xor_sync(~0u, sum, o);
            float inv = 1.f / sum;
            float* ar = A + n * M_ROWS;
            ar[lane] = e0 * inv; ar[lane + 32] = e1 * inv; ar[lane + 64] = e2 * inv;
            if (lane == 0) ar[96] = e3 * inv;
        }
    }
    __syncthreads();

    // ---- Phase 4: Z = X @ w1  (97x64) ----
    for (int t = tid; t < M_ROWS * 16; t += NTHREADS) {
        int n = t >> 4, jc = t & 15;
        float a0 = 0, a1 = 0, a2 = 0, a3 = 0;
        const float* xr = Xs + n * XS_STRIDE;
        const float* wc = w1s + jc * 4;
        #pragma unroll 4
        for (int k = 0; k < 48; k++) {
            float xv = xr[k];
            const float* w4 = wc + k * 64;
            a0 += xv * w4[0]; a1 += xv * w4[1]; a2 += xv * w4[2]; a3 += xv * w4[3];
        }
        *(float4*)(Z + n * 64 + jc * 4) = make_float4(a0, a1, a2, a3);
    }
    __syncthreads();

    // ---- Phase 5: h1 = relu(A @ Z) -> R1 (stride 64) ----
    for (int t = tid; t < M_ROWS * 16; t += NTHREADS) {
        int n = t >> 4, jc = t & 15;
        float a0 = 0, a1 = 0, a2 = 0, a3 = 0;
        const float* ar = A + n * M_ROWS;
        const float* zc = Z + jc * 4;
        #pragma unroll 4
        for (int m = 0; m < M_ROWS; m++) {
            float av = ar[m];
            const float* z4 = zc + m * 64;
            a0 += av * z4[0]; a1 += av * z4[1]; a2 += av * z4[2]; a3 += av * z4[3];
        }
        *(float4*)(R1 + n * 64 + jc * 4) =
            make_float4(fmaxf(a0, 0.f), fmaxf(a1, 0.f), fmaxf(a2, 0.f), fmaxf(a3, 0.f));
    }
    __syncthreads();

    // ---- Phase 6: epilogue (only row 0 of h2 matters) ----
    // v = A[0,:] @ h1   (64)
    if (tid < 64) {
        float acc = 0;
        #pragma unroll 4
        for (int m = 0; m < M_ROWS; m++) acc += A[m] * R1[m * 64 + tid];
        vv[tid] = acc;
    }
    __syncthreads();
    // feat = relu(v @ w2)
    if (tid < 64) {
        float acc = 0;
        #pragma unroll 4
        for (int k = 0; k < 64; k++) acc += vv[k] * w2_g[k * 64 + tid];
        feat[tid] = fmaxf(acc, 0.f);
    }
    __syncthreads();
    // g = relu(feat @ v_w1 + v_b1); out = g @ v_w2 + v_b2
    if (tid < 64) {
        float acc = v_b1[tid];
        #pragma unroll 4
        for (int k = 0; k < 64; k++) acc += feat[k] * v_w1[k * 64 + tid];
        float g = fmaxf(acc, 0.f);
        float p = g * v_w2[tid];
        #pragma unroll
        for (int o = 16; o; o >>= 1) p += __shfl_xor_sync(~0u, p, o);
        if ((tid & 31) == 0) part[tid >> 5] = p;   // disjoint scratch, no race
    }
    __syncthreads();
    if (tid == 0) out[b] = part[0] + part[1] + v_b2[0];
}

extern "C" void kernel_launch(void* const* d_in, const int* in_sizes, int n_in,
                              void* d_out, int out_size) {
    const float* state = (const float*)d_in[0];
    const float* t_w1  = (const float*)d_in[1];
    const float* t_b1  = (const float*)d_in[2];
    const float* t_w2  = (const float*)d_in[3];
    const float* t_b2  = (const float*)d_in[4];
    const float* w_a   = (const float*)d_in[5];
    const float* w1    = (const float*)d_in[6];
    const float* w2    = (const float*)d_in[7];
    const float* v_w1  = (const float*)d_in[8];
    const float* v_b1  = (const float*)d_in[9];
    const float* v_w2  = (const float*)d_in[10];
    const float* v_b2  = (const float*)d_in[11];
    float* out = (float*)d_out;

    const int smem_bytes = SMEM_FLOATS * sizeof(float);
    cudaFuncSetAttribute(value_net_kernel,
                         cudaFuncAttributeMaxDynamicSharedMemorySize, smem_bytes);
    value_net_kernel<<<BATCH, NTHREADS, smem_bytes>>>(
        state, t_w1, t_b1, t_w2, t_b2, w_a, w1, w2, v_w1, v_b1, v_w2, v_b2, out);
}

// round 3
// speedup vs baseline: 2.4664x; 2.4664x over previous
#include <cuda_runtime.h>

// Problem constants
#define BATCH      8192
#define N_AGENTS   96
#define M_ROWS     97
#define SELF_DIM   16
#define H_DIM      48
#define NTHREADS   512

// Strides
#define XS_STR   48     // Xs[100][48]  row-major, padded to 100 rows
#define XT_STR   100    // Xt[48][100]  transposed, m contiguous
#define A_STR    100    // A [100][100] scores/softmax
#define Z_STR    64     // Z [97][64]
#define Y_STR    48     // Y [100][48] (in R1)
#define H1_STR   64     // h1[97][64]  (in R1)

// SMEM layout (floats) — every base multiple of 4 (16B aligned)
#define OFF_XS   0                       // 100*48  = 4800
#define OFF_XT   (OFF_XS + 4800)         // 48*100  = 4800
#define OFF_A    (OFF_XT + 4800)         // 100*100 = 10000
#define OFF_Z    (OFF_A  + 10000)        // 97*64   = 6208
#define OFF_R1   (OFF_Z  + 6208)         // max(100*48, 97*64) = 6208
#define OFF_WA   (OFF_R1 + 6208)         // 48*48   = 2304
#define OFF_W1   (OFF_WA + 2304)         // 48*64   = 3072
#define OFF_SML  (OFF_W1 + 3072)         // scratch
#define SMEM_FLOATS (OFF_SML + 256)      // 37648 floats = 147.1 KB

__global__ __launch_bounds__(NTHREADS, 1)
void value_net_kernel(const float* __restrict__ state,
                      const float* __restrict__ t_w1, const float* __restrict__ t_b1,
                      const float* __restrict__ t_w2, const float* __restrict__ t_b2,
                      const float* __restrict__ w_a_g, const float* __restrict__ w1_g,
                      const float* __restrict__ w2_g,  const float* __restrict__ v_w1,
                      const float* __restrict__ v_b1,  const float* __restrict__ v_w2,
                      const float* __restrict__ v_b2,  float* __restrict__ out)
{
    extern __shared__ float sm[];
    float* Xs  = sm + OFF_XS;
    float* Xt  = sm + OFF_XT;
    float* A   = sm + OFF_A;
    float* Z   = sm + OFF_Z;
    float* R1  = sm + OFF_R1;      // Y then h1
    float* wa  = sm + OFF_WA;
    float* w1s = sm + OFF_W1;
    float* s_self = sm + OFF_SML;         // 16
    float* h50    = sm + OFF_SML + 16;    // 50 (pad 64)
    float* vv     = sm + OFF_SML + 80;    // 64
    float* feat   = sm + OFF_SML + 144;   // 64
    float* part   = sm + OFF_SML + 208;   // 2

    const int tid = threadIdx.x;
    const int b   = blockIdx.x;
    const float* st = state + (size_t)b * N_AGENTS * 64;

    // ---- Phase 0: load human rows -> Xs (rows 1..96) + Xt (cols 1..96), weights ----
    for (int t = tid; t < N_AGENTS * 12; t += NTHREADS) {
        int r = t / 12, c = t % 12;
        float4 v4 = *(const float4*)(st + r * 64 + SELF_DIM + c * 4);
        *(float4*)(Xs + (r + 1) * XS_STR + c * 4) = v4;        // aligned: stride 48
        // transposed scatter
        Xt[(c * 4 + 0) * XT_STR + r + 1] = v4.x;
        Xt[(c * 4 + 1) * XT_STR + r + 1] = v4.y;
        Xt[(c * 4 + 2) * XT_STR + r + 1] = v4.z;
        Xt[(c * 4 + 3) * XT_STR + r + 1] = v4.w;
    }
    for (int t = tid; t < 48 * 48; t += NTHREADS) wa[t]  = w_a_g[t];
    for (int t = tid; t < 48 * 64; t += NTHREADS) w1s[t] = w1_g[t];
    if (tid < SELF_DIM) s_self[tid] = st[tid];
    __syncthreads();

    // ---- Phase 1: tiny MLP ----
    if (tid < 50) {
        float acc = t_b1[tid];
        #pragma unroll
        for (int k = 0; k < 16; k++) acc += s_self[k] * t_w1[k * 50 + tid];
        h50[tid] = fmaxf(acc, 0.f);
    }
    __syncthreads();
    if (tid < 48) {
        float acc = t_b2[tid];
        #pragma unroll 5
        for (int k = 0; k < 50; k++) acc += h50[k] * t_w2[k * 48 + tid];
        float v = fmaxf(acc, 0.f);
        Xs[tid] = v;                  // row 0
        Xt[tid * XT_STR] = v;         // col 0
    }
    __syncthreads();

    // ---- Phase 2+4 fused: Y = X @ wa (300 jobs) and Z = X @ w1 (400 jobs) ----
    for (int t = tid; t < 700; t += NTHREADS) {
        if (t < 300) {
            int nq = t / 12, jq = t % 12;
            int n0 = nq * 4, j0 = jq * 4;
            float4 a0 = {0,0,0,0}, a1 = {0,0,0,0}, a2 = {0,0,0,0}, a3 = {0,0,0,0};
            #pragma unroll 4
            for (int k = 0; k < 48; k++) {
                float4 w4 = *(const float4*)(wa + k * 48 + j0);
                float x0 = Xs[(n0 + 0) * XS_STR + k];
                float x1 = Xs[(n0 + 1) * XS_STR + k];
                float x2 = Xs[(n0 + 2) * XS_STR + k];
                float x3 = Xs[(n0 + 3) * XS_STR + k];
                a0.x += x0*w4.x; a0.y += x0*w4.y; a0.z += x0*w4.z; a0.w += x0*w4.w;
                a1.x += x1*w4.x; a1.y += x1*w4.y; a1.z += x1*w4.z; a1.w += x1*w4.w;
                a2.x += x2*w4.x; a2.y += x2*w4.y; a2.z += x2*w4.z; a2.w += x2*w4.w;
                a3.x += x3*w4.x; a3.y += x3*w4.y; a3.z += x3*w4.z; a3.w += x3*w4.w;
            }
            *(float4*)(R1 + (n0 + 0) * Y_STR + j0) = a0;
            if (n0 + 1 < M_ROWS) *(float4*)(R1 + (n0 + 1) * Y_STR + j0) = a1;
            if (n0 + 2 < M_ROWS) *(float4*)(R1 + (n0 + 2) * Y_STR + j0) = a2;
            if (n0 + 3 < M_ROWS) *(float4*)(R1 + (n0 + 3) * Y_STR + j0) = a3;
        } else {
            int u = t - 300;
            int nq = u / 16, jq = u % 16;
            int n0 = nq * 4, j0 = jq * 4;
            float4 a0 = {0,0,0,0}, a1 = {0,0,0,0}, a2 = {0,0,0,0}, a3 = {0,0,0,0};
            #pragma unroll 4
            for (int k = 0; k < 48; k++) {
                float4 w4 = *(const float4*)(w1s + k * 64 + j0);
                float x0 = Xs[(n0 + 0) * XS_STR + k];
                float x1 = Xs[(n0 + 1) * XS_STR + k];
                float x2 = Xs[(n0 + 2) * XS_STR + k];
                float x3 = Xs[(n0 + 3) * XS_STR + k];
                a0.x += x0*w4.x; a0.y += x0*w4.y; a0.z += x0*w4.z; a0.w += x0*w4.w;
                a1.x += x1*w4.x; a1.y += x1*w4.y; a1.z += x1*w4.z; a1.w += x1*w4.w;
                a2.x += x2*w4.x; a2.y += x2*w4.y; a2.z += x2*w4.z; a2.w += x2*w4.w;
                a3.x += x3*w4.x; a3.y += x3*w4.y; a3.z += x3*w4.z; a3.w += x3*w4.w;
            }
            *(float4*)(Z + (n0 + 0) * Z_STR + j0) = a0;
            if (n0 + 1 < M_ROWS) *(float4*)(Z + (n0 + 1) * Z_STR + j0) = a1;
            if (n0 + 2 < M_ROWS) *(float4*)(Z + (n0 + 2) * Z_STR + j0) = a2;
            if (n0 + 3 < M_ROWS) *(float4*)(Z + (n0 + 3) * Z_STR + j0) = a3;
        }
    }
    __syncthreads();

    // ---- Phase 3: raw scores S = Y @ X^T -> A (625 jobs, 4x4 tiles) ----
    for (int t = tid; t < 625; t += NTHREADS) {
        int nq = t / 25, mq = t % 25;
        int n0 = nq * 4, m0 = mq * 4;
        float4 s0 = {0,0,0,0}, s1 = {0,0,0,0}, s2 = {0,0,0,0}, s3 = {0,0,0,0};
        #pragma unroll 4
        for (int k = 0; k < 48; k++) {
            float4 xm = *(const float4*)(Xt + k * XT_STR + m0);
            float y0 = R1[(n0 + 0) * Y_STR + k];
            float y1 = R1[(n0 + 1) * Y_STR + k];
            float y2 = R1[(n0 + 2) * Y_STR + k];
            float y3 = R1[(n0 + 3) * Y_STR + k];
            s0.x += y0*xm.x; s0.y += y0*xm.y; s0.z += y0*xm.z; s0.w += y0*xm.w;
            s1.x += y1*xm.x; s1.y += y1*xm.y; s1.z += y1*xm.z; s1.w += y1*xm.w;
            s2.x += y2*xm.x; s2.y += y2*xm.y; s2.z += y2*xm.z; s2.w += y2*xm.w;
            s3.x += y3*xm.x; s3.y += y3*xm.y; s3.z += y3*xm.z; s3.w += y3*xm.w;
        }
        *(float4*)(A + (n0 + 0) * A_STR + m0) = s0;
        if (n0 + 1 < M_ROWS) *(float4*)(A + (n0 + 1) * A_STR + m0) = s1;
        if (n0 + 2 < M_ROWS) *(float4*)(A + (n0 + 2) * A_STR + m0) = s2;
        if (n0 + 3 < M_ROWS) *(float4*)(A + (n0 + 3) * A_STR + m0) = s3;
    }
    __syncthreads();

    // ---- Softmax over rows of A (in place) ----
    {
        int warp = tid >> 5, lane = tid & 31;
        for (int n = warp; n < M_ROWS; n += 16) {
            float* ar = A + n * A_STR;
            float s0 = ar[lane], s1 = ar[lane + 32], s2 = ar[lane + 64];
            float s3 = ar[96];
            float mx = fmaxf(fmaxf(s0, s1), s2);
            if (lane == 0) mx = fmaxf(mx, s3);
            #pragma unroll
            for (int o = 16; o; o >>= 1) mx = fmaxf(mx, __shfl_xor_sync(~0u, mx, o));
            float e0 = __expf(s0 - mx), e1 = __expf(s1 - mx), e2 = __expf(s2 - mx);
            float e3 = __expf(s3 - mx);
            float sum = e0 + e1 + e2 + ((lane == 0) ? e3 : 0.f);
            #pragma unroll
            for (int o = 16; o; o >>= 1) sum += __shfl_xor_sync(~0u, sum, o);
            float inv = 1.f / sum;
            ar[lane] = e0 * inv; ar[lane + 32] = e1 * inv; ar[lane + 64] = e2 * inv;
            if (lane == 0) ar[96] = e3 * inv;
        }
    }
    __syncthreads();

    // ---- Phase 5: h1 = relu(A @ Z) -> R1 stride 64 (400 jobs, 4x4 tiles) ----
    for (int t = tid; t < 400; t += NTHREADS) {
        int nq = t / 16, jq = t % 16;
        int n0 = nq * 4, j0 = jq * 4;
        float4 a0 = {0,0,0,0}, a1 = {0,0,0,0}, a2 = {0,0,0,0}, a3 = {0,0,0,0};
        #pragma unroll 4
        for (int m = 0; m < M_ROWS; m++) {
            float4 z4 = *(const float4*)(Z + m * Z_STR + j0);
            float v0 = A[(n0 + 0) * A_STR + m];
            float v1 = A[(n0 + 1) * A_STR + m];
            float v2 = A[(n0 + 2) * A_STR + m];
            float v3 = A[(n0 + 3) * A_STR + m];
            a0.x += v0*z4.x; a0.y += v0*z4.y; a0.z += v0*z4.z; a0.w += v0*z4.w;
            a1.x += v1*z4.x; a1.y += v1*z4.y; a1.z += v1*z4.z; a1.w += v1*z4.w;
            a2.x += v2*z4.x; a2.y += v2*z4.y; a2.z += v2*z4.z; a2.w += v2*z4.w;
            a3.x += v3*z4.x; a3.y += v3*z4.y; a3.z += v3*z4.z; a3.w += v3*z4.w;
        }
        a0.x = fmaxf(a0.x,0.f); a0.y = fmaxf(a0.y,0.f); a0.z = fmaxf(a0.z,0.f); a0.w = fmaxf(a0.w,0.f);
        a1.x = fmaxf(a1.x,0.f); a1.y = fmaxf(a1.y,0.f); a1.z = fmaxf(a1.z,0.f); a1.w = fmaxf(a1.w,0.f);
        a2.x = fmaxf(a2.x,0.f); a2.y = fmaxf(a2.y,0.f); a2.z = fmaxf(a2.z,0.f); a2.w = fmaxf(a2.w,0.f);
        a3.x = fmaxf(a3.x,0.f); a3.y = fmaxf(a3.y,0.f); a3.z = fmaxf(a3.z,0.f); a3.w = fmaxf(a3.w,0.f);
        *(float4*)(R1 + (n0 + 0) * H1_STR + j0) = a0;
        if (n0 + 1 < M_ROWS) *(float4*)(R1 + (n0 + 1) * H1_STR + j0) = a1;
        if (n0 + 2 < M_ROWS) *(float4*)(R1 + (n0 + 2) * H1_STR + j0) = a2;
        if (n0 + 3 < M_ROWS) *(float4*)(R1 + (n0 + 3) * H1_STR + j0) = a3;
    }
    __syncthreads();

    // ---- Phase 6: epilogue (only row 0 of h2 matters) ----
    if (tid < 64) {
        float acc = 0;
        #pragma unroll 4
        for (int m = 0; m < M_ROWS; m++) acc += A[m] * R1[m * H1_STR + tid];
        vv[tid] = acc;
    }
    __syncthreads();
    if (tid < 64) {
        float acc = 0;
        #pragma unroll 4
        for (int k = 0; k < 64; k++) acc += vv[k] * w2_g[k * 64 + tid];
        feat[tid] = fmaxf(acc, 0.f);
    }
    __syncthreads();
    if (tid < 64) {
        float acc = v_b1[tid];
        #pragma unroll 4
        for (int k = 0; k < 64; k++) acc += feat[k] * v_w1[k * 64 + tid];
        float g = fmaxf(acc, 0.f);
        float p = g * v_w2[tid];
        #pragma unroll
        for (int o = 16; o; o >>= 1) p += __shfl_xor_sync(~0u, p, o);
        if ((tid & 31) == 0) part[tid >> 5] = p;
    }
    __syncthreads();
    if (tid == 0) out[b] = part[0] + part[1] + v_b2[0];
}

extern "C" void kernel_launch(void* const* d_in, const int* in_sizes, int n_in,
                              void* d_out, int out_size) {
    const float* state = (const float*)d_in[0];
    const float* t_w1  = (const float*)d_in[1];
    const float* t_b1  = (const float*)d_in[2];
    const float* t_w2  = (const float*)d_in[3];
    const float* t_b2  = (const float*)d_in[4];
    const float* w_a   = (const float*)d_in[5];
    const float* w1    = (const float*)d_in[6];
    const float* w2    = (const float*)d_in[7];
    const float* v_w1  = (const float*)d_in[8];
    const float* v_b1  = (const float*)d_in[9];
    const float* v_w2  = (const float*)d_in[10];
    const float* v_b2  = (const float*)d_in[11];
    float* out = (float*)d_out;

    const int smem_bytes = SMEM_FLOATS * sizeof(float);
    cudaFuncSetAttribute(value_net_kernel,
                         cudaFuncAttributeMaxDynamicSharedMemorySize, smem_bytes);
    value_net_kernel<<<BATCH, NTHREADS, smem_bytes>>>(
        state, t_w1, t_b1, t_w2, t_b2, w_a, w1, w2, v_w1, v_b1, v_w2, v_b2, out);
}

// round 4
// speedup vs baseline: 2.8764x; 1.1663x over previous
#include <cuda_runtime.h>

#define BATCH      8192
#define N_AGENTS   96
#define M_ROWS     97
#define SELF_DIM   16
#define NTHREADS   512

// strides
#define XS_STR   48
#define XT_STR   100
#define A_STR    100
#define Y_STR    48
#define Z_STR    64
#define H1_STR   64

// SMEM layout (floats), all bases multiple of 4
#define OFF_XS   0                 // Xs [97..100][48] rows 0-96 used: 4800
#define OFF_XT   4800              // Xt [48][100]: 4800
#define OFF_A    9600              // A  [100][100]: 10000
#define OFF_Z    19600             // Z  [100][64]: 6400
#define OFF_YH   26000             // Y [100][48] then h1 [100][64]: 6400
#define OFF_WA   32400             // 48*48 = 2304
#define OFF_W1   34704             // 48*64 = 3072
#define OFF_W2   37776             // 64*64 = 4096
#define OFF_VW1  41872             // 64*64 = 4096
#define OFF_SML  45968             // h50@0(64), pp@64(256), vv@320, feat@384, part@448
#define SMEM_FLOATS (OFF_SML + 512)   // 46480 floats = 181.6 KB

__global__ __launch_bounds__(NTHREADS, 1)
void value_net_kernel(const float* __restrict__ state,
                      const float* __restrict__ t_w1, const float* __restrict__ t_b1,
                      const float* __restrict__ t_w2, const float* __restrict__ t_b2,
                      const float* __restrict__ w_a_g, const float* __restrict__ w1_g,
                      const float* __restrict__ w2_g,  const float* __restrict__ v_w1,
                      const float* __restrict__ v_b1,  const float* __restrict__ v_w2,
                      const float* __restrict__ v_b2,  float* __restrict__ out)
{
    extern __shared__ float sm[];
    float* Xs   = sm + OFF_XS;
    float* Xt   = sm + OFF_XT;
    float* A    = sm + OFF_A;
    float* Z    = sm + OFF_Z;
    float* Y    = sm + OFF_YH;     // overlaid: Y (dead after scores), then h1
    float* H1   = sm + OFF_YH;
    float* wa   = sm + OFF_WA;
    float* w1s  = sm + OFF_W1;
    float* w2s  = sm + OFF_W2;
    float* vw1s = sm + OFF_VW1;
    float* h50  = sm + OFF_SML;
    float* pp   = sm + OFF_SML + 64;
    float* vv   = sm + OFF_SML + 320;
    float* feat = sm + OFF_SML + 384;
    float* part = sm + OFF_SML + 448;

    const int tid = threadIdx.x;
    const int b   = blockIdx.x;
    const float* st = state + (size_t)b * N_AGENTS * 64;
    const float4 zero4 = make_float4(0.f, 0.f, 0.f, 0.f);

    // ======== R0: all loads + zero pads + MLP stage 1 ========
    for (int t = tid; t < 4772; t += NTHREADS) {
        if (t < 1152) {                       // state rows 1..96 -> Xs + Xt scatter
            int r = t / 12, c = t % 12;
            float4 v4 = *(const float4*)(st + r * 64 + SELF_DIM + c * 4);
            *(float4*)(Xs + (r + 1) * XS_STR + c * 4) = v4;
            Xt[(c * 4 + 0) * XT_STR + r + 1] = v4.x;
            Xt[(c * 4 + 1) * XT_STR + r + 1] = v4.y;
            Xt[(c * 4 + 2) * XT_STR + r + 1] = v4.z;
            Xt[(c * 4 + 3) * XT_STR + r + 1] = v4.w;
        } else if (t < 1728) { int u = t - 1152; ((float4*)wa)[u]   = ((const float4*)w_a_g)[u]; }
          else if (t < 2496) { int u = t - 1728; ((float4*)w1s)[u]  = ((const float4*)w1_g)[u]; }
          else if (t < 3520) { int u = t - 2496; ((float4*)w2s)[u]  = ((const float4*)w2_g)[u]; }
          else if (t < 4544) { int u = t - 3520; ((float4*)vw1s)[u] = ((const float4*)v_w1)[u]; }
          else if (t < 4688) { int u = t - 4544; Xt[(u / 3) * XT_STR + 97 + u % 3] = 0.f; }
          else if (t < 4724) { int u = t - 4688; ((float4*)(Y + 97 * Y_STR))[u] = zero4; }
          else               { int u = t - 4724; ((float4*)(Z + 97 * Z_STR))[u] = zero4; }
    }
    if (tid < 50) {                           // MLP stage 1 (reads globals only)
        float acc = t_b1[tid];
        #pragma unroll
        for (int k = 0; k < 16; k++) acc += st[k] * t_w1[k * 50 + tid];
        h50[tid] = fmaxf(acc, 0.f);
    }
    __syncthreads();

    // ======== R0b: Y' rows 1-96  ||  (MLP2 -> Y row0, Z row0 on warps 14-15) ========
    if (tid < 288) {
        int nq = tid / 12, jq = tid % 12;
        int n0 = 1 + nq * 4, j0 = jq * 4;
        float4 a0 = zero4, a1 = zero4, a2 = zero4, a3 = zero4;
        #pragma unroll 4
        for (int k = 0; k < 48; k++) {
            float4 w4 = *(const float4*)(wa + k * 48 + j0);
            float x0 = Xs[(n0 + 0) * XS_STR + k], x1 = Xs[(n0 + 1) * XS_STR + k];
            float x2 = Xs[(n0 + 2) * XS_STR + k], x3 = Xs[(n0 + 3) * XS_STR + k];
            a0.x += x0*w4.x; a0.y += x0*w4.y; a0.z += x0*w4.z; a0.w += x0*w4.w;
            a1.x += x1*w4.x; a1.y += x1*w4.y; a1.z += x1*w4.z; a1.w += x1*w4.w;
            a2.x += x2*w4.x; a2.y += x2*w4.y; a2.z += x2*w4.z; a2.w += x2*w4.w;
            a3.x += x3*w4.x; a3.y += x3*w4.y; a3.z += x3*w4.z; a3.w += x3*w4.w;
        }
        *(float4*)(Y + (n0 + 0) * Y_STR + j0) = a0;
        *(float4*)(Y + (n0 + 1) * Y_STR + j0) = a1;
        *(float4*)(Y + (n0 + 2) * Y_STR + j0) = a2;
        *(float4*)(Y + (n0 + 3) * Y_STR + j0) = a3;
    } else if (tid >= 448) {
        int j = tid - 448;
        if (j < 48) {                          // MLP stage 2 -> Xs row0 + Xt col0
            float acc = t_b2[j];
            #pragma unroll 5
            for (int k = 0; k < 50; k++) acc += h50[k] * t_w2[k * 48 + j];
            float v = fmaxf(acc, 0.f);
            Xs[j] = v;
            Xt[j * XT_STR] = v;
        }
        asm volatile("bar.sync 1, 64;" ::: "memory");   // warps 14,15 only
        if (j < 12) {                          // Y row 0
            int j0 = j * 4;
            float4 a = zero4;
            #pragma unroll 4
            for (int k = 0; k < 48; k++) {
                float4 w4 = *(const float4*)(wa + k * 48 + j0);
                float xv = Xs[k];
                a.x += xv*w4.x; a.y += xv*w4.y; a.z += xv*w4.z; a.w += xv*w4.w;
            }
            *(float4*)(Y + j0) = a;
        } else if (j >= 16 && j < 32) {        // Z row 0
            int j0 = (j - 16) * 4;
            float4 a = zero4;
            #pragma unroll 4
            for (int k = 0; k < 48; k++) {
                float4 w4 = *(const float4*)(w1s + k * 64 + j0);
                float xv = Xs[k];
                a.x += xv*w4.x; a.y += xv*w4.y; a.z += xv*w4.z; a.w += xv*w4.w;
            }
            *(float4*)(Z + j0) = a;
        }
    }
    __syncthreads();

    // ======== R1c: scores (625) + Z' rows 1-96 (384) = 1009 jobs, ~2/thread ========
    for (int t = tid; t < 1009; t += NTHREADS) {
        if (t < 625) {
            int nq = t / 25, mq = t % 25;
            int n0 = nq * 4, m0 = mq * 4;
            float4 s0 = zero4, s1 = zero4, s2 = zero4, s3 = zero4;
            #pragma unroll 4
            for (int k = 0; k < 48; k++) {
                float4 xm = *(const float4*)(Xt + k * XT_STR + m0);
                float y0 = Y[(n0 + 0) * Y_STR + k], y1 = Y[(n0 + 1) * Y_STR + k];
                float y2 = Y[(n0 + 2) * Y_STR + k], y3 = Y[(n0 + 3) * Y_STR + k];
                s0.x += y0*xm.x; s0.y += y0*xm.y; s0.z += y0*xm.z; s0.w += y0*xm.w;
                s1.x += y1*xm.x; s1.y += y1*xm.y; s1.z += y1*xm.z; s1.w += y1*xm.w;
                s2.x += y2*xm.x; s2.y += y2*xm.y; s2.z += y2*xm.z; s2.w += y2*xm.w;
                s3.x += y3*xm.x; s3.y += y3*xm.y; s3.z += y3*xm.z; s3.w += y3*xm.w;
            }
            *(float4*)(A + (n0 + 0) * A_STR + m0) = s0;
            *(float4*)(A + (n0 + 1) * A_STR + m0) = s1;
            *(float4*)(A + (n0 + 2) * A_STR + m0) = s2;
            *(float4*)(A + (n0 + 3) * A_STR + m0) = s3;
        } else {
            int u = t - 625;
            int nq = u / 16, jq = u & 15;
            int n0 = 1 + nq * 4, j0 = jq * 4;
            float4 a0 = zero4, a1 = zero4, a2 = zero4, a3 = zero4;
            #pragma unroll 4
            for (int k = 0; k < 48; k++) {
                float4 w4 = *(const float4*)(w1s + k * 64 + j0);
                float x0 = Xs[(n0 + 0) * XS_STR + k], x1 = Xs[(n0 + 1) * XS_STR + k];
                float x2 = Xs[(n0 + 2) * XS_STR + k], x3 = Xs[(n0 + 3) * XS_STR + k];
                a0.x += x0*w4.x; a0.y += x0*w4.y; a0.z += x0*w4.z; a0.w += x0*w4.w;
                a1.x += x1*w4.x; a1.y += x1*w4.y; a1.z += x1*w4.z; a1.w += x1*w4.w;
                a2.x += x2*w4.x; a2.y += x2*w4.y; a2.z += x2*w4.z; a2.w += x2*w4.w;
                a3.x += x3*w4.x; a3.y += x3*w4.y; a3.z += x3*w4.z; a3.w += x3*w4.w;
            }
            *(float4*)(Z + (n0 + 0) * Z_STR + j0) = a0;
            *(float4*)(Z + (n0 + 1) * Z_STR + j0) = a1;
            *(float4*)(Z + (n0 + 2) * Z_STR + j0) = a2;
            *(float4*)(Z + (n0 + 3) * Z_STR + j0) = a3;
        }
    }
    __syncthreads();

    // ======== R1d: softmax rows 0-96, 2 rows per warp for ILP ========
    {
        int warp = tid >> 5, lane = tid & 31;
        #pragma unroll
        for (int base = 0; base < 96; base += 32) {
            float* r1p = A + (base + warp) * A_STR;
            float* r2p = A + (base + warp + 16) * A_STR;
            float a0 = r1p[lane], a1 = r1p[lane + 32], a2 = r1p[lane + 64], a3 = r1p[96];
            float b0 = r2p[lane], b1 = r2p[lane + 32], b2 = r2p[lane + 64], b3 = r2p[96];
            float mA = fmaxf(fmaxf(a0, a1), a2);
            float mB = fmaxf(fmaxf(b0, b1), b2);
            if (lane == 0) { mA = fmaxf(mA, a3); mB = fmaxf(mB, b3); }
            #pragma unroll
            for (int o = 16; o; o >>= 1) {
                mA = fmaxf(mA, __shfl_xor_sync(~0u, mA, o));
                mB = fmaxf(mB, __shfl_xor_sync(~0u, mB, o));
            }
            float eA0 = __expf(a0 - mA), eA1 = __expf(a1 - mA), eA2 = __expf(a2 - mA), eA3 = __expf(a3 - mA);
            float eB0 = __expf(b0 - mB), eB1 = __expf(b1 - mB), eB2 = __expf(b2 - mB), eB3 = __expf(b3 - mB);
            float sA = eA0 + eA1 + eA2 + ((lane == 0) ? eA3 : 0.f);
            float sB = eB0 + eB1 + eB2 + ((lane == 0) ? eB3 : 0.f);
            #pragma unroll
            for (int o = 16; o; o >>= 1) {
                sA += __shfl_xor_sync(~0u, sA, o);
                sB += __shfl_xor_sync(~0u, sB, o);
            }
            float iA = 1.f / sA, iB = 1.f / sB;
            r1p[lane] = eA0 * iA; r1p[lane + 32] = eA1 * iA; r1p[lane + 64] = eA2 * iA;
            r2p[lane] = eB0 * iB; r2p[lane + 32] = eB1 * iB; r2p[lane + 64] = eB2 * iB;
            if (lane == 0) { r1p[96] = eA3 * iA; r2p[96] = eB3 * iB; }
        }
        if (warp == 0) {                       // row 96
            float* rp = A + 96 * A_STR;
            float a0 = rp[lane], a1 = rp[lane + 32], a2 = rp[lane + 64], a3 = rp[96];
            float mx = fmaxf(fmaxf(a0, a1), a2);
            if (lane == 0) mx = fmaxf(mx, a3);
            #pragma unroll
            for (int o = 16; o; o >>= 1) mx = fmaxf(mx, __shfl_xor_sync(~0u, mx, o));
            float e0 = __expf(a0 - mx), e1 = __expf(a1 - mx), e2 = __expf(a2 - mx), e3 = __expf(a3 - mx);
            float s = e0 + e1 + e2 + ((lane == 0) ? e3 : 0.f);
            #pragma unroll
            for (int o = 16; o; o >>= 1) s += __shfl_xor_sync(~0u, s, o);
            float iv = 1.f / s;
            rp[lane] = e0 * iv; rp[lane + 32] = e1 * iv; rp[lane + 64] = e2 * iv;
            if (lane == 0) rp[96] = e3 * iv;
        }
    }
    __syncthreads();

    // ======== R1e: h1 = relu(A @ Z), rows 0-99 (400 jobs, K=100 with zero pads) ========
    if (tid < 400) {
        int nq = tid / 16, jq = tid & 15;
        int n0 = nq * 4, j0 = jq * 4;
        float4 a0 = zero4, a1 = zero4, a2 = zero4, a3 = zero4;
        #pragma unroll 4
        for (int m = 0; m < 100; m++) {
            float4 z4 = *(const float4*)(Z + m * Z_STR + j0);
            float v0 = A[(n0 + 0) * A_STR + m], v1 = A[(n0 + 1) * A_STR + m];
            float v2 = A[(n0 + 2) * A_STR + m], v3 = A[(n0 + 3) * A_STR + m];
            a0.x += v0*z4.x; a0.y += v0*z4.y; a0.z += v0*z4.z; a0.w += v0*z4.w;
            a1.x += v1*z4.x; a1.y += v1*z4.y; a1.z += v1*z4.z; a1.w += v1*z4.w;
            a2.x += v2*z4.x; a2.y += v2*z4.y; a2.z += v2*z4.z; a2.w += v2*z4.w;
            a3.x += v3*z4.x; a3.y += v3*z4.y; a3.z += v3*z4.z; a3.w += v3*z4.w;
        }
        a0.x=fmaxf(a0.x,0.f); a0.y=fmaxf(a0.y,0.f); a0.z=fmaxf(a0.z,0.f); a0.w=fmaxf(a0.w,0.f);
        a1.x=fmaxf(a1.x,0.f); a1.y=fmaxf(a1.y,0.f); a1.z=fmaxf(a1.z,0.f); a1.w=fmaxf(a1.w,0.f);
        a2.x=fmaxf(a2.x,0.f); a2.y=fmaxf(a2.y,0.f); a2.z=fmaxf(a2.z,0.f); a2.w=fmaxf(a2.w,0.f);
        a3.x=fmaxf(a3.x,0.f); a3.y=fmaxf(a3.y,0.f); a3.z=fmaxf(a3.z,0.f); a3.w=fmaxf(a3.w,0.f);
        *(float4*)(H1 + (n0 + 0) * H1_STR + j0) = a0;
        *(float4*)(H1 + (n0 + 1) * H1_STR + j0) = a1;
        *(float4*)(H1 + (n0 + 2) * H1_STR + j0) = a2;
        *(float4*)(H1 + (n0 + 3) * H1_STR + j0) = a3;
    }
    __syncthreads();

    // ======== Epilogue: only row 0 of h2 matters ========
    if (tid < 256) {                           // 6a partials: v = A[0,:] @ h1, k-split x4
        int c = tid & 63, ch = tid >> 6;
        int m0 = ch * 25;
        float acc = 0.f;
        #pragma unroll 5
        for (int m = m0; m < m0 + 25; m++) acc += A[m] * H1[m * H1_STR + c];
        pp[tid] = acc;
    }
    __syncthreads();
    if (tid < 64) vv[tid] = pp[tid] + pp[64 + tid] + pp[128 + tid] + pp[192 + tid];
    __syncthreads();
    if (tid < 64) {                            // feat = relu(v @ w2)
        float acc = 0.f;
        #pragma unroll 4
        for (int k = 0; k < 64; k++) acc += vv[k] * w2s[k * 64 + tid];
        feat[tid] = fmaxf(acc, 0.f);
    }
    __syncthreads();
    if (tid < 64) {                            // value = relu(feat@v_w1+b1) @ v_w2 + b2
        float acc = v_b1[tid];
        #pragma unroll 4
        for (int k = 0; k < 64; k++) acc += feat[k] * vw1s[k * 64 + tid];
        float g = fmaxf(acc, 0.f);
        float p = g * v_w2[tid];
        #pragma unroll
        for (int o = 16; o; o >>= 1) p += __shfl_xor_sync(~0u, p, o);
        if ((tid & 31) == 0) part[tid >> 5] = p;
    }
    __syncthreads();
    if (tid == 0) out[b] = part[0] + part[1] + v_b2[0];
}

extern "C" void kernel_launch(void* const* d_in, const int* in_sizes, int n_in,
                              void* d_out, int out_size) {
    const float* state = (const float*)d_in[0];
    const float* t_w1  = (const float*)d_in[1];
    const float* t_b1  = (const float*)d_in[2];
    const float* t_w2  = (const float*)d_in[3];
    const float* t_b2  = (const float*)d_in[4];
    const float* w_a   = (const float*)d_in[5];
    const float* w1    = (const float*)d_in[6];
    const float* w2    = (const float*)d_in[7];
    const float* v_w1  = (const float*)d_in[8];
    const float* v_b1  = (const float*)d_in[9];
    const float* v_w2  = (const float*)d_in[10];
    const float* v_b2  = (const float*)d_in[11];
    float* out = (float*)d_out;

    const int smem_bytes = SMEM_FLOATS * sizeof(float);
    cudaFuncSetAttribute(value_net_kernel,
                         cudaFuncAttributeMaxDynamicSharedMemorySize, smem_bytes);
    value_net_kernel<<<BATCH, NTHREADS, smem_bytes>>>(
        state, t_w1, t_b1, t_w2, t_b2, w_a, w1, w2, v_w1, v_b1, v_w2, v_b2, out);
}

// round 5
// speedup vs baseline: 4.1355x; 1.4377x over previous
#include <cuda_runtime.h>

#define BATCH    8192
#define NT       512

// ---- SMEM layout (floats); all live-region bases 16B aligned ----
// [0,4656)      Xs [97][48]          (dead after scores)  -> H1 [97][64]=6208 overlays [0,6208)
// [4656,9456)   W  [48][100]         (dead after scores)
// [9456,19156)  A  [97][100]=9700 ; early: wa49 (48*49=2352) @+0, w1s (48*64) @+2352
//               epilogue: vw1s (64*64) @+104 (A rows>=1 dead after h1)
// [19156,25364) Z  [97][64]=6208     (dead after h1) ; epilogue: w2s (64*64) @+0
// [25364,25828) scratch
#define OFF_XS   0
#define OFF_W    4656
#define OFF_A    9456
#define OFF_Z    19156
#define OFF_SML  25364
#define SMEM_FLOATS (OFF_SML + 464)

__device__ __forceinline__ void fma4(float4& c, float s, float4 v) {
    c.x += s * v.x; c.y += s * v.y; c.z += s * v.z; c.w += s * v.w;
}

__global__ __launch_bounds__(NT, 2)
void value_net_kernel(const float* __restrict__ state,
                      const float* __restrict__ t_w1, const float* __restrict__ t_b1,
                      const float* __restrict__ t_w2, const float* __restrict__ t_b2,
                      const float* __restrict__ w_a_g, const float* __restrict__ w1_g,
                      const float* __restrict__ w2_g,  const float* __restrict__ v_w1,
                      const float* __restrict__ v_b1,  const float* __restrict__ v_w2,
                      const float* __restrict__ v_b2,  float* __restrict__ out)
{
    extern __shared__ float sm[];
    float* Xs   = sm + OFF_XS;          // stride 48, rows 0..96
    float* H1   = sm + OFF_XS;          // stride 64 (written after softmax)
    float* W    = sm + OFF_W;           // stride 100, rows k=0..47
    float* A    = sm + OFF_A;           // stride 100, rows 0..96
    float* wa49 = sm + OFF_A;           // stride 49 (early lifetime)
    float* w1s  = sm + OFF_A + 2352;    // [48][64] (early lifetime)
    float* vw1s = sm + OFF_A + 104;     // [64][64] (epilogue)
    float* Z    = sm + OFF_Z;           // stride 64, rows 0..96
    float* w2s  = sm + OFF_Z;           // [64][64] (epilogue)
    float* h50  = sm + OFF_SML;
    float* pp   = sm + OFF_SML + 64;    // 256
    float* vv   = sm + OFF_SML + 320;
    float* feat = sm + OFF_SML + 384;
    float* part = sm + OFF_SML + 448;

    const int tid = threadIdx.x;
    const int b   = blockIdx.x;
    const float* st = state + (size_t)b * 96 * 64;
    const float4 z4i = make_float4(0.f, 0.f, 0.f, 0.f);

    // ======== R0: loads + MLP stage 1 (globals only) ========
    if (tid < 50) {
        float acc = t_b1[tid];
        #pragma unroll
        for (int k = 0; k < 16; k++) acc += st[k] * t_w1[k * 50 + tid];
        h50[tid] = fmaxf(acc, 0.f);
    }
    for (int t = tid; t < 2496; t += NT) {
        if (t < 1152) {                      // state rows 1..96 -> Xs
            int r = t / 12, c = t % 12;
            *(float4*)(Xs + (r + 1) * 48 + c * 4) =
                *(const float4*)(st + r * 64 + 16 + c * 4);
        } else if (t < 1728) {               // w_a -> wa49 (stride 49, scalar stores)
            int u = t - 1152; int r = u / 12, c = u % 12;
            float4 v = ((const float4*)w_a_g)[u];
            float* d = wa49 + r * 49 + c * 4;
            d[0] = v.x; d[1] = v.y; d[2] = v.z; d[3] = v.w;
        } else {                             // w1 -> w1s
            int u = t - 1728;
            ((float4*)w1s)[u] = ((const float4*)w1_g)[u];
        }
    }
    __syncthreads();

    // ======== R0b: W cols 4..99 + Z rows 1..96  ||  tail: MLP2 -> W cols 0-3, Z row 0 ========
    if (tid < 448) {
        for (int t = tid; t < 672; t += 448) {
            if (t < 288) {                   // W[k0..k0+3][m0..m0+3], m0 = 4+4*(t/12)
                int kq = t % 12, mq = t / 12;
                int k0 = kq * 4, m0 = 4 + mq * 4;
                float4 a0 = z4i, a1 = z4i, a2 = z4i, a3 = z4i;
                #pragma unroll 4
                for (int j = 0; j < 48; j++) {
                    float4 xv = make_float4(Xs[(m0 + 0) * 48 + j], Xs[(m0 + 1) * 48 + j],
                                            Xs[(m0 + 2) * 48 + j], Xs[(m0 + 3) * 48 + j]);
                    fma4(a0, wa49[(k0 + 0) * 49 + j], xv);
                    fma4(a1, wa49[(k0 + 1) * 49 + j], xv);
                    fma4(a2, wa49[(k0 + 2) * 49 + j], xv);
                    fma4(a3, wa49[(k0 + 3) * 49 + j], xv);
                }
                *(float4*)(W + (k0 + 0) * 100 + m0) = a0;
                *(float4*)(W + (k0 + 1) * 100 + m0) = a1;
                *(float4*)(W + (k0 + 2) * 100 + m0) = a2;
                *(float4*)(W + (k0 + 3) * 100 + m0) = a3;
            } else {                         // Z rows 1..96
                int u = t - 288;
                int n0 = 1 + (u >> 4) * 4, j0 = (u & 15) * 4;
                float4 a0 = z4i, a1 = z4i, a2 = z4i, a3 = z4i;
                #pragma unroll 4
                for (int k = 0; k < 48; k++) {
                    float4 w4 = *(const float4*)(w1s + k * 64 + j0);
                    fma4(a0, Xs[(n0 + 0) * 48 + k], w4);
                    fma4(a1, Xs[(n0 + 1) * 48 + k], w4);
                    fma4(a2, Xs[(n0 + 2) * 48 + k], w4);
                    fma4(a3, Xs[(n0 + 3) * 48 + k], w4);
                }
                *(float4*)(Z + (n0 + 0) * 64 + j0) = a0;
                *(float4*)(Z + (n0 + 1) * 64 + j0) = a1;
                *(float4*)(Z + (n0 + 2) * 64 + j0) = a2;
                *(float4*)(Z + (n0 + 3) * 64 + j0) = a3;
            }
        }
    } else {
        int j = tid - 448;
        if (j < 48) {                        // MLP stage 2 -> Xs row 0
            float acc = t_b2[j];
            #pragma unroll 5
            for (int k = 0; k < 50; k++) acc += h50[k] * t_w2[k * 48 + j];
            Xs[j] = fmaxf(acc, 0.f);
        }
        asm volatile("bar.sync 1, 64;" ::: "memory");
        if (j < 12) {                        // W cols 0..3 (need X rows 0..3)
            int k0 = j * 4;
            float4 a0 = z4i, a1 = z4i, a2 = z4i, a3 = z4i;
            #pragma unroll 4
            for (int jj = 0; jj < 48; jj++) {
                float4 xv = make_float4(Xs[jj], Xs[48 + jj], Xs[96 + jj], Xs[144 + jj]);
                fma4(a0, wa49[(k0 + 0) * 49 + jj], xv);
                fma4(a1, wa49[(k0 + 1) * 49 + jj], xv);
                fma4(a2, wa49[(k0 + 2) * 49 + jj], xv);
                fma4(a3, wa49[(k0 + 3) * 49 + jj], xv);
            }
            *(float4*)(W + (k0 + 0) * 100) = a0;
            *(float4*)(W + (k0 + 1) * 100) = a1;
            *(float4*)(W + (k0 + 2) * 100) = a2;
            *(float4*)(W + (k0 + 3) * 100) = a3;
        } else if (j < 28) {                 // Z row 0
            int j0 = (j - 12) * 4;
            float4 a = z4i;
            #pragma unroll 4
            for (int k = 0; k < 48; k++)
                fma4(a, Xs[k], *(const float4*)(w1s + k * 64 + j0));
            *(float4*)(Z + j0) = a;
        }
    }
    __syncthreads();

    // ======== Scores: A = X @ W  (nq uniform per warp; 800 slots, 625 real) ========
    for (int t = tid; t < 800; t += NT) {
        int nq = t >> 5, mq = t & 31;
        if (mq >= 25) continue;
        int n0 = nq * 4, m0 = mq * 4;
        float4 s0 = z4i, s1 = z4i, s2 = z4i, s3 = z4i;
        #pragma unroll 4
        for (int k = 0; k < 48; k++) {
            float4 w4 = *(const float4*)(W + k * 100 + m0);
            fma4(s0, Xs[(n0 + 0) * 48 + k], w4);
            fma4(s1, Xs[(n0 + 1) * 48 + k], w4);
            fma4(s2, Xs[(n0 + 2) * 48 + k], w4);
            fma4(s3, Xs[(n0 + 3) * 48 + k], w4);
        }
        *(float4*)(A + (n0 + 0) * 100 + m0) = s0;
        if (n0 + 1 <= 96) *(float4*)(A + (n0 + 1) * 100 + m0) = s1;
        if (n0 + 2 <= 96) *(float4*)(A + (n0 + 2) * 100 + m0) = s2;
        if (n0 + 3 <= 96) *(float4*)(A + (n0 + 3) * 100 + m0) = s3;
    }
    __syncthreads();

    // ======== Softmax rows 0..96 (2 rows/warp for ILP) ========
    {
        int warp = tid >> 5, lane = tid & 31;
        #pragma unroll
        for (int base = 0; base < 96; base += 32) {
            float* r1p = A + (base + warp) * 100;
            float* r2p = A + (base + warp + 16) * 100;
            float a0 = r1p[lane], a1 = r1p[lane + 32], a2 = r1p[lane + 64], a3 = r1p[96];
            float b0 = r2p[lane], b1 = r2p[lane + 32], b2 = r2p[lane + 64], b3 = r2p[96];
            float mA = fmaxf(fmaxf(a0, a1), a2);
            float mB = fmaxf(fmaxf(b0, b1), b2);
            if (lane == 0) { mA = fmaxf(mA, a3); mB = fmaxf(mB, b3); }
            #pragma unroll
            for (int o = 16; o; o >>= 1) {
                mA = fmaxf(mA, __shfl_xor_sync(~0u, mA, o));
                mB = fmaxf(mB, __shfl_xor_sync(~0u, mB, o));
            }
            float eA0 = __expf(a0 - mA), eA1 = __expf(a1 - mA), eA2 = __expf(a2 - mA), eA3 = __expf(a3 - mA);
            float eB0 = __expf(b0 - mB), eB1 = __expf(b1 - mB), eB2 = __expf(b2 - mB), eB3 = __expf(b3 - mB);
            float sA = eA0 + eA1 + eA2 + ((lane == 0) ? eA3 : 0.f);
            float sB = eB0 + eB1 + eB2 + ((lane == 0) ? eB3 : 0.f);
            #pragma unroll
            for (int o = 16; o; o >>= 1) {
                sA += __shfl_xor_sync(~0u, sA, o);
                sB += __shfl_xor_sync(~0u, sB, o);
            }
            float iA = 1.f / sA, iB = 1.f / sB;
            r1p[lane] = eA0 * iA; r1p[lane + 32] = eA1 * iA; r1p[lane + 64] = eA2 * iA;
            r2p[lane] = eB0 * iB; r2p[lane + 32] = eB1 * iB; r2p[lane + 64] = eB2 * iB;
            if (lane == 0) { r1p[96] = eA3 * iA; r2p[96] = eB3 * iB; }
        }
        if (warp == 0) {
            float* rp = A + 96 * 100;
            float a0 = rp[lane], a1 = rp[lane + 32], a2 = rp[lane + 64], a3 = rp[96];
            float mx = fmaxf(fmaxf(a0, a1), a2);
            if (lane == 0) mx = fmaxf(mx, a3);
            #pragma unroll
            for (int o = 16; o; o >>= 1) mx = fmaxf(mx, __shfl_xor_sync(~0u, mx, o));
            float e0 = __expf(a0 - mx), e1 = __expf(a1 - mx), e2 = __expf(a2 - mx), e3 = __expf(a3 - mx);
            float s = e0 + e1 + e2 + ((lane == 0) ? e3 : 0.f);
            #pragma unroll
            for (int o = 16; o; o >>= 1) s += __shfl_xor_sync(~0u, s, o);
            float iv = 1.f / s;
            rp[lane] = e0 * iv; rp[lane + 32] = e1 * iv; rp[lane + 64] = e2 * iv;
            if (lane == 0) rp[96] = e3 * iv;
        }
    }
    __syncthreads();

    // ======== h1 = relu(A @ Z) with dot4 over contraction dim (A m-contiguous) ========
    if (tid < 400) {
        if (tid < 384) {
            int n0 = (tid >> 4) * 4, j0 = (tid & 15) * 4;
            float4 c0 = z4i, c1 = z4i, c2 = z4i, c3 = z4i;
            for (int m = 0; m < 96; m += 4) {
                float4 a0 = *(const float4*)(A + (n0 + 0) * 100 + m);
                float4 a1 = *(const float4*)(A + (n0 + 1) * 100 + m);
                float4 a2 = *(const float4*)(A + (n0 + 2) * 100 + m);
                float4 a3 = *(const float4*)(A + (n0 + 3) * 100 + m);
                float4 z0 = *(const float4*)(Z + (m + 0) * 64 + j0);
                float4 z1 = *(const float4*)(Z + (m + 1) * 64 + j0);
                float4 z2 = *(const float4*)(Z + (m + 2) * 64 + j0);
                float4 z3 = *(const float4*)(Z + (m + 3) * 64 + j0);
                fma4(c0, a0.x, z0); fma4(c0, a0.y, z1); fma4(c0, a0.z, z2); fma4(c0, a0.w, z3);
                fma4(c1, a1.x, z0); fma4(c1, a1.y, z1); fma4(c1, a1.z, z2); fma4(c1, a1.w, z3);
                fma4(c2, a2.x, z0); fma4(c2, a2.y, z1); fma4(c2, a2.z, z2); fma4(c2, a2.w, z3);
                fma4(c3, a3.x, z0); fma4(c3, a3.y, z1); fma4(c3, a3.z, z2); fma4(c3, a3.w, z3);
            }
            {   // tail m = 96
                float4 zt = *(const float4*)(Z + 96 * 64 + j0);
                fma4(c0, A[(n0 + 0) * 100 + 96], zt);
                fma4(c1, A[(n0 + 1) * 100 + 96], zt);
                fma4(c2, A[(n0 + 2) * 100 + 96], zt);
                fma4(c3, A[(n0 + 3) * 100 + 96], zt);
            }
            c0.x=fmaxf(c0.x,0.f); c0.y=fmaxf(c0.y,0.f); c0.z=fmaxf(c0.z,0.f); c0.w=fmaxf(c0.w,0.f);
            c1.x=fmaxf(c1.x,0.f); c1.y=fmaxf(c1.y,0.f); c1.z=fmaxf(c1.z,0.f); c1.w=fmaxf(c1.w,0.f);
            c2.x=fmaxf(c2.x,0.f); c2.y=fmaxf(c2.y,0.f); c2.z=fmaxf(c2.z,0.f); c2.w=fmaxf(c2.w,0.f);
            c3.x=fmaxf(c3.x,0.f); c3.y=fmaxf(c3.y,0.f); c3.z=fmaxf(c3.z,0.f); c3.w=fmaxf(c3.w,0.f);
            *(float4*)(H1 + (n0 + 0) * 64 + j0) = c0;
            *(float4*)(H1 + (n0 + 1) * 64 + j0) = c1;
            *(float4*)(H1 + (n0 + 2) * 64 + j0) = c2;
            *(float4*)(H1 + (n0 + 3) * 64 + j0) = c3;
        } else {                              // row 96
            int j0 = (tid - 384) * 4;
            float4 c0 = z4i;
            for (int m = 0; m < 96; m += 4) {
                float4 a0 = *(const float4*)(A + 96 * 100 + m);
                fma4(c0, a0.x, *(const float4*)(Z + (m + 0) * 64 + j0));
                fma4(c0, a0.y, *(const float4*)(Z + (m + 1) * 64 + j0));
                fma4(c0, a0.z, *(const float4*)(Z + (m + 2) * 64 + j0));
                fma4(c0, a0.w, *(const float4*)(Z + (m + 3) * 64 + j0));
            }
            fma4(c0, A[96 * 100 + 96], *(const float4*)(Z + 96 * 64 + j0));
            c0.x=fmaxf(c0.x,0.f); c0.y=fmaxf(c0.y,0.f); c0.z=fmaxf(c0.z,0.f); c0.w=fmaxf(c0.w,0.f);
            *(float4*)(H1 + 96 * 64 + j0) = c0;
        }
    }
    __syncthreads();

    // ======== Epilogue: 6a partials || load w2/v_w1 into freed smem ========
    if (tid < 256) {
        int c = tid & 63, ch = tid >> 6;
        int m0 = ch * 25, me = (ch == 3) ? 97 : m0 + 25;
        float acc = 0.f;
        for (int m = m0; m < me; m++) acc += A[m] * H1[m * 64 + c];
        pp[tid] = acc;
    } else {
        int u = tid - 256;
        for (int i = u; i < 1024; i += 256) {
            ((float4*)w2s)[i]  = ((const float4*)w2_g)[i];
            ((float4*)vw1s)[i] = ((const float4*)v_w1)[i];
        }
    }
    __syncthreads();
    if (tid < 64) vv[tid] = pp[tid] + pp[64 + tid] + pp[128 + tid] + pp[192 + tid];
    __syncthreads();
    if (tid < 64) {
        float acc = 0.f;
        #pragma unroll 4
        for (int k = 0; k < 64; k++) acc += vv[k] * w2s[k * 64 + tid];
        feat[tid] = fmaxf(acc, 0.f);
    }
    __syncthreads();
    if (tid < 64) {
        float acc = v_b1[tid];
        #pragma unroll 4
        for (int k = 0; k < 64; k++) acc += feat[k] * vw1s[k * 64 + tid];
        float g = fmaxf(acc, 0.f);
        float p = g * v_w2[tid];
        #pragma unroll
        for (int o = 16; o; o >>= 1) p += __shfl_xor_sync(~0u, p, o);
        if ((tid & 31) == 0) part[tid >> 5] = p;
    }
    __syncthreads();
    if (tid == 0) out[b] = part[0] + part[1] + v_b2[0];
}

extern "C" void kernel_launch(void* const* d_in, const int* in_sizes, int n_in,
                              void* d_out, int out_size) {
    const float* state = (const float*)d_in[0];
    const float* t_w1  = (const float*)d_in[1];
    const float* t_b1  = (const float*)d_in[2];
    const float* t_w2  = (const float*)d_in[3];
    const float* t_b2  = (const float*)d_in[4];
    const float* w_a   = (const float*)d_in[5];
    const float* w1    = (const float*)d_in[6];
    const float* w2    = (const float*)d_in[7];
    const float* v_w1  = (const float*)d_in[8];
    const float* v_b1  = (const float*)d_in[9];
    const float* v_w2  = (const float*)d_in[10];
    const float* v_b2  = (const float*)d_in[11];
    float* out = (float*)d_out;

    const int smem_bytes = SMEM_FLOATS * sizeof(float);
    cudaFuncSetAttribute(value_net_kernel,
                         cudaFuncAttributeMaxDynamicSharedMemorySize, smem_bytes);
    value_net_kernel<<<BATCH, NT, smem_bytes>>>(
        state, t_w1, t_b1, t_w2, t_b2, w_a, w1, w2, v_w1, v_b1, v_w2, v_b2, out);
}

// round 6
// speedup vs baseline: 4.2387x; 1.0249x over previous
#include <cuda_runtime.h>

#define BATCH    8192
#define NT       512

// ---- SMEM layout (floats); all live-region bases 16B aligned ----
// [0,4656)      Xs [97][48]  (dead after scores) -> H1 [97][64] overlays [0,6208)
// [4656,9456)   W  [48][100] (dead after scores)
// [9456,19156)  A  [97][100] ; early: wa49 @+0 (48*49), w1s @+2352 (48*64)
//               epilogue: vw1s @+104 (A rows>=1 dead after h1)
// [19156,25364) Z  [97][64]  ; epilogue: w2s @+0
// [25364,25828) scratch
#define OFF_XS   0
#define OFF_W    4656
#define OFF_A    9456
#define OFF_Z    19156
#define OFF_SML  25364
#define SMEM_FLOATS (OFF_SML + 464)

__device__ __forceinline__ void fma4(float4& c, float s, float4 v) {
    c.x += s * v.x; c.y += s * v.y; c.z += s * v.z; c.w += s * v.w;
}

__global__ __launch_bounds__(NT, 2)
void value_net_kernel(const float* __restrict__ state,
                      const float* __restrict__ t_w1, const float* __restrict__ t_b1,
                      const float* __restrict__ t_w2, const float* __restrict__ t_b2,
                      const float* __restrict__ w_a_g, const float* __restrict__ w1_g,
                      const float* __restrict__ w2_g,  const float* __restrict__ v_w1,
                      const float* __restrict__ v_b1,  const float* __restrict__ v_w2,
                      const float* __restrict__ v_b2,  float* __restrict__ out)
{
    extern __shared__ float sm[];
    float* Xs   = sm + OFF_XS;
    float* H1   = sm + OFF_XS;
    float* W    = sm + OFF_W;
    float* A    = sm + OFF_A;
    float* wa49 = sm + OFF_A;
    float* w1s  = sm + OFF_A + 2352;
    float* vw1s = sm + OFF_A + 104;
    float* Z    = sm + OFF_Z;
    float* w2s  = sm + OFF_Z;
    float* h50  = sm + OFF_SML;
    float* pp   = sm + OFF_SML + 64;
    float* vv   = sm + OFF_SML + 320;
    float* feat = sm + OFF_SML + 384;
    float* part = sm + OFF_SML + 448;

    const int tid = threadIdx.x;
    const int b   = blockIdx.x;
    const float* st = state + (size_t)b * 96 * 64;
    const float4 z4i = make_float4(0.f, 0.f, 0.f, 0.f);

    // ======== R0: loads + MLP stage 1 ========
    if (tid < 50) {
        float acc = t_b1[tid];
        #pragma unroll
        for (int k = 0; k < 16; k++) acc += st[k] * t_w1[k * 50 + tid];
        h50[tid] = fmaxf(acc, 0.f);
    }
    for (int t = tid; t < 2496; t += NT) {
        if (t < 1152) {
            int r = t / 12, c = t % 12;
            *(float4*)(Xs + (r + 1) * 48 + c * 4) =
                *(const float4*)(st + r * 64 + 16 + c * 4);
        } else if (t < 1728) {
            int u = t - 1152; int r = u / 12, c = u % 12;
            float4 v = ((const float4*)w_a_g)[u];
            float* d = wa49 + r * 49 + c * 4;
            d[0] = v.x; d[1] = v.y; d[2] = v.z; d[3] = v.w;
        } else {
            int u = t - 1728;
            ((float4*)w1s)[u] = ((const float4*)w1_g)[u];
        }
    }
    __syncthreads();

    // ======== R0b: W cols 4..99 + Z rows 1..96 || tail: MLP2 -> W cols 0-3, Z row 0 ========
    if (tid < 448) {
        for (int t = tid; t < 672; t += 448) {
            if (t < 288) {                   // W[k0..k0+3][m0..m0+3]
                int kq = t % 12, mq = t / 12;
                int k0 = kq * 4, m0 = 4 + mq * 4;
                float4 acc[4] = {z4i, z4i, z4i, z4i};
                #pragma unroll 3
                for (int j = 0; j < 48; j += 4) {
                    float4 x0 = *(const float4*)(Xs + (m0 + 0) * 48 + j);
                    float4 x1 = *(const float4*)(Xs + (m0 + 1) * 48 + j);
                    float4 x2 = *(const float4*)(Xs + (m0 + 2) * 48 + j);
                    float4 x3 = *(const float4*)(Xs + (m0 + 3) * 48 + j);
                    #pragma unroll
                    for (int c = 0; c < 4; c++) {
                        const float* wr = wa49 + (k0 + c) * 49 + j;
                        float w0 = wr[0], w1 = wr[1], w2 = wr[2], w3 = wr[3];
                        acc[c].x += w0*x0.x + w1*x0.y + w2*x0.z + w3*x0.w;
                        acc[c].y += w0*x1.x + w1*x1.y + w2*x1.z + w3*x1.w;
                        acc[c].z += w0*x2.x + w1*x2.y + w2*x2.z + w3*x2.w;
                        acc[c].w += w0*x3.x + w1*x3.y + w2*x3.z + w3*x3.w;
                    }
                }
                #pragma unroll
                for (int c = 0; c < 4; c++)
                    *(float4*)(W + (k0 + c) * 100 + m0) = acc[c];
            } else {                         // Z rows 1..96, k-vectorized
                int u = t - 288;
                int n0 = 1 + (u >> 4) * 4, j0 = (u & 15) * 4;
                float4 a0 = z4i, a1 = z4i, a2 = z4i, a3 = z4i;
                #pragma unroll 3
                for (int k = 0; k < 48; k += 4) {
                    float4 x0 = *(const float4*)(Xs + (n0 + 0) * 48 + k);
                    float4 x1 = *(const float4*)(Xs + (n0 + 1) * 48 + k);
                    float4 x2 = *(const float4*)(Xs + (n0 + 2) * 48 + k);
                    float4 x3 = *(const float4*)(Xs + (n0 + 3) * 48 + k);
                    float4 w;
                    w = *(const float4*)(w1s + (k + 0) * 64 + j0);
                    fma4(a0, x0.x, w); fma4(a1, x1.x, w); fma4(a2, x2.x, w); fma4(a3, x3.x, w);
                    w = *(const float4*)(w1s + (k + 1) * 64 + j0);
                    fma4(a0, x0.y, w); fma4(a1, x1.y, w); fma4(a2, x2.y, w); fma4(a3, x3.y, w);
                    w = *(const float4*)(w1s + (k + 2) * 64 + j0);
                    fma4(a0, x0.z, w); fma4(a1, x1.z, w); fma4(a2, x2.z, w); fma4(a3, x3.z, w);
                    w = *(const float4*)(w1s + (k + 3) * 64 + j0);
                    fma4(a0, x0.w, w); fma4(a1, x1.w, w); fma4(a2, x2.w, w); fma4(a3, x3.w, w);
                }
                *(float4*)(Z + (n0 + 0) * 64 + j0) = a0;
                *(float4*)(Z + (n0 + 1) * 64 + j0) = a1;
                *(float4*)(Z + (n0 + 2) * 64 + j0) = a2;
                *(float4*)(Z + (n0 + 3) * 64 + j0) = a3;
            }
        }
    } else {
        int j = tid - 448;
        if (j < 48) {                        // MLP stage 2 -> Xs row 0
            float acc = t_b2[j];
            #pragma unroll 5
            for (int k = 0; k < 50; k++) acc += h50[k] * t_w2[k * 48 + j];
            Xs[j] = fmaxf(acc, 0.f);
        }
        asm volatile("bar.sync 1, 64;" ::: "memory");
        if (j < 12) {                        // W cols 0..3 (X rows 0..3)
            int k0 = j * 4;
            float4 acc[4] = {z4i, z4i, z4i, z4i};
            #pragma unroll 3
            for (int jj = 0; jj < 48; jj += 4) {
                float4 x0 = *(const float4*)(Xs + jj);
                float4 x1 = *(const float4*)(Xs + 48 + jj);
                float4 x2 = *(const float4*)(Xs + 96 + jj);
                float4 x3 = *(const float4*)(Xs + 144 + jj);
                #pragma unroll
                for (int c = 0; c < 4; c++) {
                    const float* wr = wa49 + (k0 + c) * 49 + jj;
                    float w0 = wr[0], w1 = wr[1], w2 = wr[2], w3 = wr[3];
                    acc[c].x += w0*x0.x + w1*x0.y + w2*x0.z + w3*x0.w;
                    acc[c].y += w0*x1.x + w1*x1.y + w2*x1.z + w3*x1.w;
                    acc[c].z += w0*x2.x + w1*x2.y + w2*x2.z + w3*x2.w;
                    acc[c].w += w0*x3.x + w1*x3.y + w2*x3.z + w3*x3.w;
                }
            }
            #pragma unroll
            for (int c = 0; c < 4; c++)
                *(float4*)(W + (k0 + c) * 100) = acc[c];
        } else if (j < 28) {                 // Z row 0
            int j0 = (j - 12) * 4;
            float4 a = z4i;
            #pragma unroll 4
            for (int k = 0; k < 48; k++)
                fma4(a, Xs[k], *(const float4*)(w1s + k * 64 + j0));
            *(float4*)(Z + j0) = a;
        }
    }
    __syncthreads();

    // ======== Scores: A = X @ W (k-vectorized; nq warp-uniform broadcast) ========
    for (int t = tid; t < 800; t += NT) {
        int nq = t >> 5, mq = t & 31;
        int mqc = (mq < 25) ? mq : 24;       // clamp: inactive lanes redo job 24
        int n0 = nq * 4, m0 = mqc * 4;
        float4 s0 = z4i, s1 = z4i, s2 = z4i, s3 = z4i;
        #pragma unroll 3
        for (int k = 0; k < 48; k += 4) {
            float4 x0 = *(const float4*)(Xs + (n0 + 0) * 48 + k);   // broadcast
            float4 x1 = *(const float4*)(Xs + (n0 + 1) * 48 + k);
            float4 x2 = *(const float4*)(Xs + (n0 + 2) * 48 + k);
            float4 x3 = *(const float4*)(Xs + (n0 + 3) * 48 + k);
            float4 w;
            w = *(const float4*)(W + (k + 0) * 100 + m0);
            fma4(s0, x0.x, w); fma4(s1, x1.x, w); fma4(s2, x2.x, w); fma4(s3, x3.x, w);
            w = *(const float4*)(W + (k + 1) * 100 + m0);
            fma4(s0, x0.y, w); fma4(s1, x1.y, w); fma4(s2, x2.y, w); fma4(s3, x3.y, w);
            w = *(const float4*)(W + (k + 2) * 100 + m0);
            fma4(s0, x0.z, w); fma4(s1, x1.z, w); fma4(s2, x2.z, w); fma4(s3, x3.z, w);
            w = *(const float4*)(W + (k + 3) * 100 + m0);
            fma4(s0, x0.w, w); fma4(s1, x1.w, w); fma4(s2, x2.w, w); fma4(s3, x3.w, w);
        }
        if (mq < 25) {
            *(float4*)(A + (n0 + 0) * 100 + m0) = s0;
            if (n0 + 1 <= 96) *(float4*)(A + (n0 + 1) * 100 + m0) = s1;
            if (n0 + 2 <= 96) *(float4*)(A + (n0 + 2) * 100 + m0) = s2;
            if (n0 + 3 <= 96) *(float4*)(A + (n0 + 3) * 100 + m0) = s3;
        }
    }
    __syncthreads();

    // ======== Softmax rows 0..96 (2 rows/warp) ========
    {
        int warp = tid >> 5, lane = tid & 31;
        #pragma unroll
        for (int base = 0; base < 96; base += 32) {
            float* r1p = A + (base + warp) * 100;
            float* r2p = A + (base + warp + 16) * 100;
            float a0 = r1p[lane], a1 = r1p[lane + 32], a2 = r1p[lane + 64], a3 = r1p[96];
            float b0 = r2p[lane], b1 = r2p[lane + 32], b2 = r2p[lane + 64], b3 = r2p[96];
            float mA = fmaxf(fmaxf(a0, a1), a2);
            float mB = fmaxf(fmaxf(b0, b1), b2);
            if (lane == 0) { mA = fmaxf(mA, a3); mB = fmaxf(mB, b3); }
            #pragma unroll
            for (int o = 16; o; o >>= 1) {
                mA = fmaxf(mA, __shfl_xor_sync(~0u, mA, o));
                mB = fmaxf(mB, __shfl_xor_sync(~0u, mB, o));
            }
            float eA0 = __expf(a0 - mA), eA1 = __expf(a1 - mA), eA2 = __expf(a2 - mA), eA3 = __expf(a3 - mA);
            float eB0 = __expf(b0 - mB), eB1 = __expf(b1 - mB), eB2 = __expf(b2 - mB), eB3 = __expf(b3 - mB);
            float sA = eA0 + eA1 + eA2 + ((lane == 0) ? eA3 : 0.f);
            float sB = eB0 + eB1 + eB2 + ((lane == 0) ? eB3 : 0.f);
            #pragma unroll
            for (int o = 16; o; o >>= 1) {
                sA += __shfl_xor_sync(~0u, sA, o);
                sB += __shfl_xor_sync(~0u, sB, o);
            }
            float iA = 1.f / sA, iB = 1.f / sB;
            r1p[lane] = eA0 * iA; r1p[lane + 32] = eA1 * iA; r1p[lane + 64] = eA2 * iA;
            r2p[lane] = eB0 * iB; r2p[lane + 32] = eB1 * iB; r2p[lane + 64] = eB2 * iB;
            if (lane == 0) { r1p[96] = eA3 * iA; r2p[96] = eB3 * iB; }
        }
        if (warp == 0) {
            float* rp = A + 96 * 100;
            float a0 = rp[lane], a1 = rp[lane + 32], a2 = rp[lane + 64], a3 = rp[96];
            float mx = fmaxf(fmaxf(a0, a1), a2);
            if (lane == 0) mx = fmaxf(mx, a3);
            #pragma unroll
            for (int o = 16; o; o >>= 1) mx = fmaxf(mx, __shfl_xor_sync(~0u, mx, o));
            float e0 = __expf(a0 - mx), e1 = __expf(a1 - mx), e2 = __expf(a2 - mx), e3 = __expf(a3 - mx);
            float s = e0 + e1 + e2 + ((lane == 0) ? e3 : 0.f);
            #pragma unroll
            for (int o = 16; o; o >>= 1) s += __shfl_xor_sync(~0u, s, o);
            float iv = 1.f / s;
            rp[lane] = e0 * iv; rp[lane + 32] = e1 * iv; rp[lane + 64] = e2 * iv;
            if (lane == 0) rp[96] = e3 * iv;
        }
    }
    __syncthreads();

    // ======== h1 = relu(A @ Z), dot4 over contraction ========
    if (tid < 400) {
        if (tid < 384) {
            int n0 = (tid >> 4) * 4, j0 = (tid & 15) * 4;
            float4 c0 = z4i, c1 = z4i, c2 = z4i, c3 = z4i;
            for (int m = 0; m < 96; m += 4) {
                float4 a0 = *(const float4*)(A + (n0 + 0) * 100 + m);
                float4 a1 = *(const float4*)(A + (n0 + 1) * 100 + m);
                float4 a2 = *(const float4*)(A + (n0 + 2) * 100 + m);
                float4 a3 = *(const float4*)(A + (n0 + 3) * 100 + m);
                float4 z0 = *(const float4*)(Z + (m + 0) * 64 + j0);
                float4 z1 = *(const float4*)(Z + (m + 1) * 64 + j0);
                float4 z2 = *(const float4*)(Z + (m + 2) * 64 + j0);
                float4 z3 = *(const float4*)(Z + (m + 3) * 64 + j0);
                fma4(c0, a0.x, z0); fma4(c0, a0.y, z1); fma4(c0, a0.z, z2); fma4(c0, a0.w, z3);
                fma4(c1, a1.x, z0); fma4(c1, a1.y, z1); fma4(c1, a1.z, z2); fma4(c1, a1.w, z3);
                fma4(c2, a2.x, z0); fma4(c2, a2.y, z1); fma4(c2, a2.z, z2); fma4(c2, a2.w, z3);
                fma4(c3, a3.x, z0); fma4(c3, a3.y, z1); fma4(c3, a3.z, z2); fma4(c3, a3.w, z3);
            }
            {
                float4 zt = *(const float4*)(Z + 96 * 64 + j0);
                fma4(c0, A[(n0 + 0) * 100 + 96], zt);
                fma4(c1, A[(n0 + 1) * 100 + 96], zt);
                fma4(c2, A[(n0 + 2) * 100 + 96], zt);
                fma4(c3, A[(n0 + 3) * 100 + 96], zt);
            }
            c0.x=fmaxf(c0.x,0.f); c0.y=fmaxf(c0.y,0.f); c0.z=fmaxf(c0.z,0.f); c0.w=fmaxf(c0.w,0.f);
            c1.x=fmaxf(c1.x,0.f); c1.y=fmaxf(c1.y,0.f); c1.z=fmaxf(c1.z,0.f); c1.w=fmaxf(c1.w,0.f);
            c2.x=fmaxf(c2.x,0.f); c2.y=fmaxf(c2.y,0.f); c2.z=fmaxf(c2.z,0.f); c2.w=fmaxf(c2.w,0.f);
            c3.x=fmaxf(c3.x,0.f); c3.y=fmaxf(c3.y,0.f); c3.z=fmaxf(c3.z,0.f); c3.w=fmaxf(c3.w,0.f);
            *(float4*)(H1 + (n0 + 0) * 64 + j0) = c0;
            *(float4*)(H1 + (n0 + 1) * 64 + j0) = c1;
            *(float4*)(H1 + (n0 + 2) * 64 + j0) = c2;
            *(float4*)(H1 + (n0 + 3) * 64 + j0) = c3;
        } else {
            int j0 = (tid - 384) * 4;
            float4 c0 = z4i;
            for (int m = 0; m < 96; m += 4) {
                float4 a0 = *(const float4*)(A + 96 * 100 + m);
                fma4(c0, a0.x, *(const float4*)(Z + (m + 0) * 64 + j0));
                fma4(c0, a0.y, *(const float4*)(Z + (m + 1) * 64 + j0));
                fma4(c0, a0.z, *(const float4*)(Z + (m + 2) * 64 + j0));
                fma4(c0, a0.w, *(const float4*)(Z + (m + 3) * 64 + j0));
            }
            fma4(c0, A[96 * 100 + 96], *(const float4*)(Z + 96 * 64 + j0));
            c0.x=fmaxf(c0.x,0.f); c0.y=fmaxf(c0.y,0.f); c0.z=fmaxf(c0.z,0.f); c0.w=fmaxf(c0.w,0.f);
            *(float4*)(H1 + 96 * 64 + j0) = c0;
        }
    }
    __syncthreads();

    // ======== Epilogue: 6a partials || load w2/v_w1 into freed smem ========
    if (tid < 256) {
        int c = tid & 63, ch = tid >> 6;
        int m0 = ch * 25, me = (ch == 3) ? 97 : m0 + 25;
        float acc = 0.f;
        for (int m = m0; m < me; m++) acc += A[m] * H1[m * 64 + c];
        pp[tid] = acc;
    } else {
        int u = tid - 256;
        for (int i = u; i < 1024; i += 256) {
            ((float4*)w2s)[i]  = ((const float4*)w2_g)[i];
            ((float4*)vw1s)[i] = ((const float4*)v_w1)[i];
        }
    }
    __syncthreads();
    if (tid < 64) vv[tid] = pp[tid] + pp[64 + tid] + pp[128 + tid] + pp[192 + tid];
    __syncthreads();
    if (tid < 64) {
        float acc = 0.f;
        #pragma unroll 4
        for (int k = 0; k < 64; k++) acc += vv[k] * w2s[k * 64 + tid];
        feat[tid] = fmaxf(acc, 0.f);
    }
    __syncthreads();
    if (tid < 64) {
        float acc = v_b1[tid];
        #pragma unroll 4
        for (int k = 0; k < 64; k++) acc += feat[k] * vw1s[k * 64 + tid];
        float g = fmaxf(acc, 0.f);
        float p = g * v_w2[tid];
        #pragma unroll
        for (int o = 16; o; o >>= 1) p += __shfl_xor_sync(~0u, p, o);
        if ((tid & 31) == 0) part[tid >> 5] = p;
    }
    __syncthreads();
    if (tid == 0) out[b] = part[0] + part[1] + v_b2[0];
}

extern "C" void kernel_launch(void* const* d_in, const int* in_sizes, int n_in,
                              void* d_out, int out_size) {
    const float* state = (const float*)d_in[0];
    const float* t_w1  = (const float*)d_in[1];
    const float* t_b1  = (const float*)d_in[2];
    const float* t_w2  = (const float*)d_in[3];
    const float* t_b2  = (const float*)d_in[4];
    const float* w_a   = (const float*)d_in[5];
    const float* w1    = (const float*)d_in[6];
    const float* w2    = (const float*)d_in[7];
    const float* v_w1  = (const float*)d_in[8];
    const float* v_b1  = (const float*)d_in[9];
    const float* v_w2  = (const float*)d_in[10];
    const float* v_b2  = (const float*)d_in[11];
    float* out = (float*)d_out;

    const int smem_bytes = SMEM_FLOATS * sizeof(float);
    cudaFuncSetAttribute(value_net_kernel,
                         cudaFuncAttributeMaxDynamicSharedMemorySize, smem_bytes);
    value_net_kernel<<<BATCH, NT, smem_bytes>>>(
        state, t_w1, t_b1, t_w2, t_b2, w_a, w1, w2, v_w1, v_b1, v_w2, v_b2, out);
}